// round 8
// baseline (speedup 1.0000x reference)
#include <cuda_runtime.h>
#include <cuda_bf16.h>

// AngularDescriptor via moment expansion:
//   q[i,d,l] = 0.5 * ( sum_p a_{lp} T_p[d]  -  sum_j g_ij[d]^2 )
//   T_p[d]   = sum_{|alpha|=p} w_alpha (sum_j g_ij[d] * u_j^alpha)^2
// One warp per atom, grid-stride with EXACT balance: 625 blocks x 8 warps
// = 5000 warps, each does exactly 2 atoms (single wave on 148 SMs).
// Phase 1: lanes 0..19 build per-neighbor g[8] + 20 unit-vector monomials,
//          written with 7 STS.128 per lane (row stride 28 floats).
// Phase 2: lane = d*4+grp accumulates 5 moments; per neighbor iteration only
//          3 LDS (g scalar, float4 monomial block, scalar 5th monomial),
//          all conflict-free. 6 FMA/iter.
// Epilogue: weighted squares -> T buckets, 8-shfl butterfly over the 4-lane
//          d-group, Legendre combine, coalesced 128B store per warp.

#define WPB 8  // warps (atoms in flight) per block

// weight of monomial (grp*5+m) into bucket (T0,T1,T2,T3)
__constant__ float4 WSEL[20] = {
    {1.f,0.f,0.f,0.f},                                          // 1
    {0.f,1.f,0.f,0.f},{0.f,1.f,0.f,0.f},{0.f,1.f,0.f,0.f},     // x y z
    {0.f,0.f,1.f,0.f},{0.f,0.f,1.f,0.f},{0.f,0.f,1.f,0.f},     // x2 y2 z2->? (x2 in grp0 slot4)
    {0.f,0.f,2.f,0.f},{0.f,0.f,2.f,0.f},{0.f,0.f,2.f,0.f},     // xy xz yz
    {0.f,0.f,0.f,1.f},{0.f,0.f,0.f,1.f},{0.f,0.f,0.f,1.f},     // x3 y3 z3
    {0.f,0.f,0.f,3.f},{0.f,0.f,0.f,3.f},{0.f,0.f,0.f,3.f},     // x2y x2z y2x
    {0.f,0.f,0.f,3.f},{0.f,0.f,0.f,3.f},{0.f,0.f,0.f,3.f},     // y2z z2x z2y
    {0.f,0.f,0.f,6.f}                                           // xyz
};
__constant__ float4 ACOEF[4] = {
    { 1.0f,  0.0f, 0.0f, 0.0f},   // P0
    { 0.0f,  1.0f, 0.0f, 0.0f},   // P1
    {-0.5f,  0.0f, 1.5f, 0.0f},   // P2
    { 0.0f, -1.5f, 0.0f, 2.5f}    // P3
};

__global__ __launch_bounds__(WPB * 32) void ang_kernel(
    const int*   __restrict__ types,
    const float* __restrict__ pos,
    const int*   __restrict__ nbr,
    const float* __restrict__ ctab,
    float*       __restrict__ out,
    int natoms)
{
    // row stride 28 floats (112B, 16B-aligned); layout per neighbor row:
    // [0:8) g[8] as 2 float4 | [8+4g : 12+4g) monomial block of group g | [24:28) 5th monomials
    __shared__ __align__(16) float sh[WPB][20 * 28];
    const int warp = threadIdx.x >> 5;
    const int lane = threadIdx.x & 31;
    float* S = sh[warp];

    const int d   = lane >> 2;
    const int grp = lane & 3;
    const float* Rg  = S + d;            // g pointer (row 0)
    const float* Rm4 = S + 8 + 4 * grp;  // float4 monomial block
    const float* Rm5 = S + 24 + grp;     // 5th monomial

    const int warp_stride = gridDim.x * WPB;

    for (int atom = blockIdx.x * WPB + warp; atom < natoms; atom += warp_stride) {

        // ---- Phase 1: per-neighbor g[8] + monomials (lanes 0..19) ----
        if (lane < 20) {
            const int   ti  = types[atom];
            const float pix = pos[atom * 3 + 0];
            const float piy = pos[atom * 3 + 1];
            const float piz = pos[atom * 3 + 2];

            const int n = nbr[atom * 20 + lane];
            const float dx = pos[n * 3 + 0] - pix;
            const float dy = pos[n * 3 + 1] - piy;
            const float dz = pos[n * 3 + 2] - piz;
            const float r2 = dx * dx + dy * dy + dz * dz;
            const float rinv = rsqrtf(r2);
            const float r  = r2 * rinv;

            const float fc = (r < 5.0f) ? fmaf(0.5f, __cosf(r * 0.6283185307179586f), 0.5f)
                                        : 0.0f;
            const float xr = fmaf(r, 0.2f, -1.0f);
            const float xx = fmaf(2.0f * xr, xr, -1.0f);
            const float h  = 0.5f * fc;

            float f[8];
            {
                float tp = 1.0f, tc = xx;
                f[0] = (tp + 1.0f) * h;
                f[1] = (tc + 1.0f) * h;
                #pragma unroll
                for (int k = 2; k < 8; k++) {
                    const float tn = fmaf(2.0f * xx, tc, -tp);
                    f[k] = (tn + 1.0f) * h;
                    tp = tc; tc = tn;
                }
            }

            const int tj = types[n];
            const float4* c4 = reinterpret_cast<const float4*>(ctab + (ti * 4 + tj) * 64);
            float g[8];
            #pragma unroll
            for (int dd = 0; dd < 8; dd++) {
                const float4 a = c4[dd * 2 + 0];
                const float4 b = c4[dd * 2 + 1];
                g[dd] = a.x * f[0] + a.y * f[1] + a.z * f[2] + a.w * f[3]
                      + b.x * f[4] + b.y * f[5] + b.z * f[6] + b.w * f[7];
            }

            const float x = dx * rinv, y = dy * rinv, z = dz * rinv;
            const float x2 = x * x, y2 = y * y, z2 = z * z;
            const float xy = x * y, xz = x * z, yz = y * z;

            float4* R = reinterpret_cast<float4*>(S + lane * 28);
            R[0] = make_float4(g[0], g[1], g[2], g[3]);
            R[1] = make_float4(g[4], g[5], g[6], g[7]);
            R[2] = make_float4(1.0f,     x,       y,       z);       // grp0 block
            R[3] = make_float4(y2,       z2,      xy,      xz);      // grp1 block
            R[4] = make_float4(x2 * x,   y2 * y,  z2 * z,  x2 * y);  // grp2 block
            R[5] = make_float4(y2 * x,   y2 * z,  z2 * x,  z2 * y);  // grp3 block
            R[6] = make_float4(x2,       yz,      x2 * z,  xy * z);  // 5th monomials
        }
        __syncwarp();

        // ---- Phase 2: moment accumulation (3 LDS + 6 FMA per neighbor) ----
        float M0 = 0.f, M1 = 0.f, M2 = 0.f, M3 = 0.f, M4 = 0.f, D = 0.f;
        #pragma unroll
        for (int j = 0; j < 20; j++) {
            const float  g  = Rg[j * 28];
            const float4 m4 = *reinterpret_cast<const float4*>(Rm4 + j * 28);
            const float  m5 = Rm5[j * 28];
            D  = fmaf(g, g,    D);
            M0 = fmaf(g, m4.x, M0);
            M1 = fmaf(g, m4.y, M1);
            M2 = fmaf(g, m4.z, M2);
            M3 = fmaf(g, m4.w, M3);
            M4 = fmaf(g, m5,   M4);
        }
        __syncwarp();

        // ---- Epilogue: weighted squares into T buckets ----
        float T0 = 0.f, T1 = 0.f, T2 = 0.f, T3 = 0.f;
        {
            const float4* W = WSEL + grp * 5;
            float s; float4 w;
            s = M0 * M0; w = W[0];
            T0 = fmaf(s, w.x, T0); T1 = fmaf(s, w.y, T1); T2 = fmaf(s, w.z, T2); T3 = fmaf(s, w.w, T3);
            s = M1 * M1; w = W[1];
            T0 = fmaf(s, w.x, T0); T1 = fmaf(s, w.y, T1); T2 = fmaf(s, w.z, T2); T3 = fmaf(s, w.w, T3);
            s = M2 * M2; w = W[2];
            T0 = fmaf(s, w.x, T0); T1 = fmaf(s, w.y, T1); T2 = fmaf(s, w.z, T2); T3 = fmaf(s, w.w, T3);
            s = M3 * M3; w = W[3];
            T0 = fmaf(s, w.x, T0); T1 = fmaf(s, w.y, T1); T2 = fmaf(s, w.z, T2); T3 = fmaf(s, w.w, T3);
            s = M4 * M4; w = W[4];
            T0 = fmaf(s, w.x, T0); T1 = fmaf(s, w.y, T1); T2 = fmaf(s, w.z, T2); T3 = fmaf(s, w.w, T3);
        }

        // butterfly over the 4-lane d-group
        T0 += __shfl_xor_sync(0xffffffffu, T0, 1);
        T0 += __shfl_xor_sync(0xffffffffu, T0, 2);
        T1 += __shfl_xor_sync(0xffffffffu, T1, 1);
        T1 += __shfl_xor_sync(0xffffffffu, T1, 2);
        T2 += __shfl_xor_sync(0xffffffffu, T2, 1);
        T2 += __shfl_xor_sync(0xffffffffu, T2, 2);
        T3 += __shfl_xor_sync(0xffffffffu, T3, 1);
        T3 += __shfl_xor_sync(0xffffffffu, T3, 2);

        const float4 a = ACOEF[grp];
        float q = a.x * T0;
        q = fmaf(a.y, T1, q);
        q = fmaf(a.z, T2, q);
        q = fmaf(a.w, T3, q);
        out[atom * 32 + lane] = 0.5f * (q - D);
    }
}

extern "C" void kernel_launch(void* const* d_in, const int* in_sizes, int n_in,
                              void* d_out, int out_size) {
    const int*   types = (const int*)  d_in[0];
    const float* pos   = (const float*)d_in[1];
    const int*   nbrs  = (const int*)  d_in[2];
    const float* ctab  = (const float*)d_in[3];
    float*       out   = (float*)      d_out;

    const int natoms = in_sizes[0];
    // exactly 2 atoms per warp when natoms = 10000: 625 blocks x 8 warps
    int blocks = (natoms + 2 * WPB - 1) / (2 * WPB);
    if (blocks < 1) blocks = 1;
    ang_kernel<<<blocks, WPB * 32>>>(types, pos, nbrs, ctab, out, natoms);
}